// round 11
// baseline (speedup 1.0000x reference)
#include <cuda_runtime.h>

// Wallclock-best architecture (R10): plain-LDG streaming + shuffle for the
// shifted pred element. This round: unroll 4 -> 8 (deeper load batching room
// for ptxas; regs have headroom) and explicit __ldg on pred.
// Fused "last block finishes" finalize, deterministic.

static constexpr int BLOCKS  = 148 * 8;   // 1184 CTAs
static constexpr int THREADS = 256;

__device__ float        g_partials[BLOCKS];
__device__ unsigned int g_done_count;      // zero-init; reset each call

__global__ __launch_bounds__(THREADS) void trajloss_shfl8_kernel(
    const float* __restrict__ pred,   // N+1 elements
    const float* __restrict__ xs,     // N elements
    const float* __restrict__ ys,     // N elements
    float* __restrict__ out,
    int n4)                           // N / 4
{
    const float4* __restrict__ pred4 = reinterpret_cast<const float4*>(pred);
    const float4* __restrict__ x4    = reinterpret_cast<const float4*>(xs);
    const float4* __restrict__ y4    = reinterpret_cast<const float4*>(ys);

    float acc0 = 0.0f, acc1 = 0.0f;

    const int stride = BLOCKS * THREADS;
    const int lane   = threadIdx.x & 31;
    int idx = blockIdx.x * THREADS + threadIdx.x;

    // stride % 32 == 0 and warp bases are 32-aligned, so a multiple-of-32
    // bound keeps the loop guard warp-uniform (shuffle-safe).
    const int bound = n4 & ~31;

    #pragma unroll 8
    for (int i = idx; i < bound; i += stride) {
        float4 p  = __ldg(&pred4[i]);
        float4 xv = __ldcs(&x4[i]);
        float4 yv = __ldcs(&y4[i]);

        // pred[4i+4] = next lane's p.x; lane 31 loads across the warp boundary
        // (same cache line as the next warp's pred4 load -> L1 hit).
        float pn = __shfl_down_sync(0xFFFFFFFFu, p.x, 1);
        if (lane == 31) pn = __ldg(&pred[i * 4 + 4]);

        float dx0 = xv.x - p.x, dx1 = xv.y - p.y;
        float dx2 = xv.z - p.z, dx3 = xv.w - p.w;
        float dy0 = yv.x - p.y, dy1 = yv.y - p.z;
        float dy2 = yv.z - p.w, dy3 = yv.w - pn;

        acc0 = fmaf(dx0, dx0, acc0); acc1 = fmaf(dy0, dy0, acc1);
        acc0 = fmaf(dx1, dx1, acc0); acc1 = fmaf(dy1, dy1, acc1);
        acc0 = fmaf(dx2, dx2, acc0); acc1 = fmaf(dy2, dy2, acc1);
        acc0 = fmaf(dx3, dx3, acc0); acc1 = fmaf(dy3, dy3, acc1);
    }

    // Shuffle-free remainder (n4 not multiple of 32; zero iters for N=2^24).
    for (int i = (idx >= bound ? idx : idx + ((bound - idx + stride - 1) / stride) * stride);
         i < n4; i += stride) {
        float4 p  = __ldg(&pred4[i]);
        float4 xv = __ldcs(&x4[i]);
        float4 yv = __ldcs(&y4[i]);
        float  pn = __ldg(&pred[i * 4 + 4]);

        float dx0 = xv.x - p.x, dx1 = xv.y - p.y;
        float dx2 = xv.z - p.z, dx3 = xv.w - p.w;
        float dy0 = yv.x - p.y, dy1 = yv.y - p.z;
        float dy2 = yv.z - p.w, dy3 = yv.w - pn;

        acc0 = fmaf(dx0, dx0, acc0); acc1 = fmaf(dy0, dy0, acc1);
        acc0 = fmaf(dx1, dx1, acc0); acc1 = fmaf(dy1, dy1, acc1);
        acc0 = fmaf(dx2, dx2, acc0); acc1 = fmaf(dy2, dy2, acc1);
        acc0 = fmaf(dx3, dx3, acc0); acc1 = fmaf(dy3, dy3, acc1);
    }

    float acc = acc0 + acc1;

    // ---- intra-block reduction ----
    #pragma unroll
    for (int off = 16; off > 0; off >>= 1)
        acc += __shfl_xor_sync(0xFFFFFFFFu, acc, off);

    __shared__ float warp_sums[THREADS / 32];
    __shared__ bool  is_last;
    int wid = threadIdx.x >> 5;
    if (lane == 0) warp_sums[wid] = acc;
    __syncthreads();

    if (wid == 0) {
        float v = (lane < THREADS / 32) ? warp_sums[lane] : 0.0f;
        #pragma unroll
        for (int off = 4; off > 0; off >>= 1)
            v += __shfl_xor_sync(0xFFFFFFFFu, v, off);
        if (lane == 0) {
            g_partials[blockIdx.x] = v;
            __threadfence();
            unsigned int prev = atomicAdd(&g_done_count, 1u);
            is_last = (prev == (unsigned int)(BLOCKS - 1));
        }
    }
    __syncthreads();

    // ---- last block reduces all partials ----
    if (is_last) {
        float t = 0.0f;
        for (int k = threadIdx.x; k < BLOCKS; k += THREADS)
            t += g_partials[k];

        #pragma unroll
        for (int off = 16; off > 0; off >>= 1)
            t += __shfl_xor_sync(0xFFFFFFFFu, t, off);

        if (lane == 0) warp_sums[wid] = t;
        __syncthreads();

        if (wid == 0) {
            float v = (lane < THREADS / 32) ? warp_sums[lane] : 0.0f;
            #pragma unroll
            for (int off = 4; off > 0; off >>= 1)
                v += __shfl_xor_sync(0xFFFFFFFFu, v, off);
            if (lane == 0) {
                out[0] = v;
                g_done_count = 0;     // graph-replay safe reset
            }
        }
    }
}

extern "C" void kernel_launch(void* const* d_in, const int* in_sizes, int n_in,
                              void* d_out, int out_size)
{
    const float* pred = (const float*)d_in[0];   // N+1
    const float* xs   = (const float*)d_in[1];   // N
    const float* ys   = (const float*)d_in[2];   // N
    float* out        = (float*)d_out;

    int n  = in_sizes[1];
    int n4 = n >> 2;

    trajloss_shfl8_kernel<<<BLOCKS, THREADS>>>(pred, xs, ys, out, n4);
}

// round 12
// speedup vs baseline: 1.2767x; 1.2767x over previous
#include <cuda_runtime.h>

// R10 architecture (wallclock-best: plain-LDG + shuffle for shifted pred,
// unroll 4) with the grid resized to exactly ONE resident wave:
// regs=40 -> 6 CTAs/SM -> 148*6 = 888 CTAs. No partial second wave tail.
// Fused "last block finishes" finalize, deterministic.

static constexpr int BLOCKS  = 148 * 6;   // 888 CTAs = exactly 1 wave @ 40 regs
static constexpr int THREADS = 256;

__device__ float        g_partials[BLOCKS];
__device__ unsigned int g_done_count;      // zero-init; reset each call

__global__ __launch_bounds__(THREADS) void trajloss_wave_kernel(
    const float* __restrict__ pred,   // N+1 elements
    const float* __restrict__ xs,     // N elements
    const float* __restrict__ ys,     // N elements
    float* __restrict__ out,
    int n4)                           // N / 4
{
    const float4* __restrict__ pred4 = reinterpret_cast<const float4*>(pred);
    const float4* __restrict__ x4    = reinterpret_cast<const float4*>(xs);
    const float4* __restrict__ y4    = reinterpret_cast<const float4*>(ys);

    float acc0 = 0.0f, acc1 = 0.0f;

    const int stride = BLOCKS * THREADS;
    const int lane   = threadIdx.x & 31;
    int idx = blockIdx.x * THREADS + threadIdx.x;

    // stride % 32 == 0 and warp bases are 32-aligned -> multiple-of-32 bound
    // keeps the loop guard warp-uniform (shuffle-safe).
    const int bound = n4 & ~31;

    #pragma unroll 4
    for (int i = idx; i < bound; i += stride) {
        float4 p  = pred4[i];
        float4 xv = __ldcs(&x4[i]);
        float4 yv = __ldcs(&y4[i]);

        // pred[4i+4] = next lane's p.x; lane 31 loads across the warp boundary.
        float pn = __shfl_down_sync(0xFFFFFFFFu, p.x, 1);
        if (lane == 31) pn = __ldg(&pred[i * 4 + 4]);

        float dx0 = xv.x - p.x, dx1 = xv.y - p.y;
        float dx2 = xv.z - p.z, dx3 = xv.w - p.w;
        float dy0 = yv.x - p.y, dy1 = yv.y - p.z;
        float dy2 = yv.z - p.w, dy3 = yv.w - pn;

        acc0 = fmaf(dx0, dx0, acc0); acc1 = fmaf(dy0, dy0, acc1);
        acc0 = fmaf(dx1, dx1, acc0); acc1 = fmaf(dy1, dy1, acc1);
        acc0 = fmaf(dx2, dx2, acc0); acc1 = fmaf(dy2, dy2, acc1);
        acc0 = fmaf(dx3, dx3, acc0); acc1 = fmaf(dy3, dy3, acc1);
    }

    // Shuffle-free remainder (zero iterations for N = 2^24).
    for (int i = (idx >= bound ? idx : idx + ((bound - idx + stride - 1) / stride) * stride);
         i < n4; i += stride) {
        float4 p  = pred4[i];
        float4 xv = __ldcs(&x4[i]);
        float4 yv = __ldcs(&y4[i]);
        float  pn = __ldg(&pred[i * 4 + 4]);

        float dx0 = xv.x - p.x, dx1 = xv.y - p.y;
        float dx2 = xv.z - p.z, dx3 = xv.w - p.w;
        float dy0 = yv.x - p.y, dy1 = yv.y - p.z;
        float dy2 = yv.z - p.w, dy3 = yv.w - pn;

        acc0 = fmaf(dx0, dx0, acc0); acc1 = fmaf(dy0, dy0, acc1);
        acc0 = fmaf(dx1, dx1, acc0); acc1 = fmaf(dy1, dy1, acc1);
        acc0 = fmaf(dx2, dx2, acc0); acc1 = fmaf(dy2, dy2, acc1);
        acc0 = fmaf(dx3, dx3, acc0); acc1 = fmaf(dy3, dy3, acc1);
    }

    float acc = acc0 + acc1;

    // ---- intra-block reduction ----
    #pragma unroll
    for (int off = 16; off > 0; off >>= 1)
        acc += __shfl_xor_sync(0xFFFFFFFFu, acc, off);

    __shared__ float warp_sums[THREADS / 32];
    __shared__ bool  is_last;
    int wid = threadIdx.x >> 5;
    if (lane == 0) warp_sums[wid] = acc;
    __syncthreads();

    if (wid == 0) {
        float v = (lane < THREADS / 32) ? warp_sums[lane] : 0.0f;
        #pragma unroll
        for (int off = 4; off > 0; off >>= 1)
            v += __shfl_xor_sync(0xFFFFFFFFu, v, off);
        if (lane == 0) {
            g_partials[blockIdx.x] = v;
            __threadfence();
            unsigned int prev = atomicAdd(&g_done_count, 1u);
            is_last = (prev == (unsigned int)(BLOCKS - 1));
        }
    }
    __syncthreads();

    // ---- last block reduces all partials ----
    if (is_last) {
        float t = 0.0f;
        for (int k = threadIdx.x; k < BLOCKS; k += THREADS)
            t += g_partials[k];

        #pragma unroll
        for (int off = 16; off > 0; off >>= 1)
            t += __shfl_xor_sync(0xFFFFFFFFu, t, off);

        if (lane == 0) warp_sums[wid] = t;
        __syncthreads();

        if (wid == 0) {
            float v = (lane < THREADS / 32) ? warp_sums[lane] : 0.0f;
            #pragma unroll
            for (int off = 4; off > 0; off >>= 1)
                v += __shfl_xor_sync(0xFFFFFFFFu, v, off);
            if (lane == 0) {
                out[0] = v;
                g_done_count = 0;     // graph-replay safe reset
            }
        }
    }
}

extern "C" void kernel_launch(void* const* d_in, const int* in_sizes, int n_in,
                              void* d_out, int out_size)
{
    const float* pred = (const float*)d_in[0];   // N+1
    const float* xs   = (const float*)d_in[1];   // N
    const float* ys   = (const float*)d_in[2];   // N
    float* out        = (float*)d_out;

    int n  = in_sizes[1];
    int n4 = n >> 2;

    trajloss_wave_kernel<<<BLOCKS, THREADS>>>(pred, xs, ys, out, n4);
}